// round 9
// baseline (speedup 1.0000x reference)
#include <cuda_runtime.h>

// Spatial correlation: out[b, di*9+dj, i, j] = (1/256) * sum_c x[b,c,i,j] * y[b,c,i+di-4, j+dj-4]
// x,y: [16, 256, 64, 64] f32, zero padding.
//
// Round-6 design:
//  - FFMA2 (fma.rn.f32x2): 2 MACs/instr, parity-split accumulator pairing so only
//    even-aligned y pairs are needed.
//  - Thread: 8 j-pixels x 1 di x 9 dj = 72 f32 accumulators (packed as f32x2).
//  - Block: 144 thr = 8jg x 2ti x 9dg, TI=2 rows; grid 32x16=512, 3 blocks/SM.
//  - y via cp.async ring (3 stages x 4 channels), SCOLS=76 padding + lane remap
//    => conflict-free LDS.128 strips.
//  - x via register LDG prefetch (distance 1), bypasses smem.

#define SROWS 10          // TI + 8 halo
#define SCOLS 76          // 72 used + 4 pad (conflict-free phase mapping)
#define YF (SROWS * SCOLS)       // 760 floats / channel
#define CPS 4                    // channels per stage
#define STAGE_F (CPS * YF)       // 3040 floats
#define STAGES 3
#define NTHREADS 144
#define NSTAGES_TOT 64           // 256 / CPS

__device__ __forceinline__ void cp16(unsigned saddr, const float* g, int nbytes) {
    asm volatile("cp.async.ca.shared.global [%0], [%1], 16, %2;\n"
                 :: "r"(saddr), "l"(g), "r"(nbytes));
}
#define COMMIT() asm volatile("cp.async.commit_group;\n" ::: "memory")
#define WAIT1()  asm volatile("cp.async.wait_group 1;\n" ::: "memory")
#define FMA2(acc, a, b) asm("fma.rn.f32x2 %0, %1, %2, %0;" : "+l"(acc) : "l"(a), "l"(b))
#define PACK2(d, lo, hi) asm("mov.b64 %0, {%1, %2};" : "=l"(d) : "f"(lo), "f"(hi))
#define UNPACK2(lo, hi, s) asm("mov.b64 {%0, %1}, %2;" : "=f"(lo), "=f"(hi) : "l"(s))

__global__ __launch_bounds__(NTHREADS, 3)
void corr_kernel(const float* __restrict__ x,
                 const float* __restrict__ y,
                 float* __restrict__ out) {
    __shared__ __align__(16) float sm[STAGES * STAGE_F];   // 36480 B

    const int tid = threadIdx.x;
    // lane remap for conflict-free LDS.128 phases:
    const int ti = (tid >> 2) & 1;                    // 0..1
    const int dg = tid >> 4;                          // 0..8 (= warp id)
    const int jg = (tid & 3) | (((tid >> 3) & 1) << 2); // 0..7
    const int b   = blockIdx.y;
    const int gi0 = blockIdx.x * 2;
    const int i   = gi0 + ti;
    const int j0  = jg * 8;

    const float* xb = x + (size_t)b * 1048576;
    const float* yb = y + (size_t)b * 1048576;
    const unsigned smbase = (unsigned)__cvta_generic_to_shared(sm);

    // ---- cp.async chunk descriptors: 720 chunks/stage = 5 per thread ----
    unsigned cdst[5]; int cbyt[5], coff[5], cch[5];
#pragma unroll
    for (int k = 0; k < 5; k++) {
        int q  = tid + k * NTHREADS;
        int ch = q / 180, m = q % 180;
        int r  = m / 18,  c4 = m % 18;      // row 0..9, col-chunk 0..17 (col = c4*4, global gc = c4*4-4)
        int gr = gi0 - 4 + r;
        bool ok = (gr >= 0) && (gr < 64) && (c4 >= 1) && (c4 <= 16);
        cbyt[k] = ok ? 16 : 0;
        coff[k] = ok ? gr * 64 + c4 * 4 - 4 : 0;
        cch[k]  = ch;
        cdst[k] = (unsigned)((ch * YF + r * SCOLS + c4 * 4) * 4);
    }

#define REFILL(S) do { unsigned _bo = (unsigned)(((S) % STAGES) * (STAGE_F * 4)); \
    _Pragma("unroll") \
    for (int k = 0; k < 5; k++) \
        cp16(smbase + _bo + cdst[k], \
             yb + (size_t)((S) * CPS + cch[k]) * 4096 + coff[k], cbyt[k]); \
} while (0)

    // ---- accumulators ----
    unsigned long long accE[5][4];   // d = 0,2,4,6,8 : pairs (0,1)(2,3)(4,5)(6,7)
    unsigned long long accO[4][3];   // d = 1,3,5,7   : pairs (1,2)(3,4)(5,6)
    float accOs[4][2];               // d odd         : scalar p0, p7
#pragma unroll
    for (int e = 0; e < 5; e++)
#pragma unroll
        for (int p = 0; p < 4; p++) accE[e][p] = 0ull;
#pragma unroll
    for (int o = 0; o < 4; o++) {
        accO[o][0] = accO[o][1] = accO[o][2] = 0ull;
        accOs[o][0] = accOs[o][1] = 0.0f;
    }

    // ---- prologue: 2 stages in flight + x channel 0 ----
    REFILL(0); COMMIT();
    REFILL(1); COMMIT();
    const float* xrow = xb + i * 64 + j0;
    float4 xn0 = *(const float4*)(xrow);
    float4 xn1 = *(const float4*)(xrow + 4);

    for (int s = 0; s < NSTAGES_TOT; s++) {
        WAIT1();
        __syncthreads();
        if (s + 2 < NSTAGES_TOT) REFILL(s + 2);
        COMMIT();

        const float* st = sm + (s % STAGES) * STAGE_F;
#pragma unroll
        for (int cc = 0; cc < CPS; cc++) {
            const int c = s * CPS + cc;
            // x: consume prefetched, issue next
            float4 xc0 = xn0, xc1 = xn1;
            const int cn = (c < 255) ? c + 1 : 255;
            xn0 = *(const float4*)(xrow + (size_t)cn * 4096);
            xn1 = *(const float4*)(xrow + (size_t)cn * 4096 + 4);

            // x pairs
            unsigned long long xe[4], xo[3];
            PACK2(xe[0], xc0.x, xc0.y); PACK2(xe[1], xc0.z, xc0.w);
            PACK2(xe[2], xc1.x, xc1.y); PACK2(xe[3], xc1.z, xc1.w);
            PACK2(xo[0], xc0.y, xc0.z); PACK2(xo[1], xc0.w, xc1.x);
            PACK2(xo[2], xc1.y, xc1.z);

            // y strip: 16 floats (conflict-free LDS.128 x4)
            const float* yr = st + cc * YF + (ti + dg) * SCOLS + j0;
            float4 f0 = *(const float4*)(yr);
            float4 f1 = *(const float4*)(yr + 4);
            float4 f2 = *(const float4*)(yr + 8);
            float4 f3 = *(const float4*)(yr + 12);
            float w[16] = {f0.x, f0.y, f0.z, f0.w, f1.x, f1.y, f1.z, f1.w,
                           f2.x, f2.y, f2.z, f2.w, f3.x, f3.y, f3.z, f3.w};
            unsigned long long E[8];
#pragma unroll
            for (int k = 0; k < 8; k++) PACK2(E[k], w[2 * k], w[2 * k + 1]);

            // even d: 4 FFMA2 each; pair index (d + 2p)/2 = e + p
#pragma unroll
            for (int e = 0; e < 5; e++) {
#pragma unroll
                for (int p = 0; p < 4; p++)
                    FMA2(accE[e][p], xe[p], E[e + p]);
            }
            // odd d = 2o+1: 3 FFMA2 (pairs (1,2)(3,4)(5,6), E index o+q+1) + 2 scalar FFMA
#pragma unroll
            for (int o = 0; o < 4; o++) {
                const int d = 2 * o + 1;
#pragma unroll
                for (int q = 0; q < 3; q++)
                    FMA2(accO[o][q], xo[q], E[o + q + 1]);
                accOs[o][0] = fmaf(xc0.x, w[d],     accOs[o][0]);
                accOs[o][1] = fmaf(xc1.w, w[d + 7], accOs[o][1]);
            }
        }
    }

    // ---- epilogue: unpack, scale 1/256, store ----
    const float scale = 1.0f / 256.0f;
    float* ob = out + ((size_t)b * 81 + dg * 9) * 4096 + i * 64 + j0;
#pragma unroll
    for (int e = 0; e < 5; e++) {
        const int d = 2 * e;
        float v[8];
#pragma unroll
        for (int p = 0; p < 4; p++) UNPACK2(v[2 * p], v[2 * p + 1], accE[e][p]);
        float4 s0 = {v[0] * scale, v[1] * scale, v[2] * scale, v[3] * scale};
        float4 s1 = {v[4] * scale, v[5] * scale, v[6] * scale, v[7] * scale};
        *(float4*)(ob + (size_t)d * 4096)     = s0;
        *(float4*)(ob + (size_t)d * 4096 + 4) = s1;
    }
#pragma unroll
    for (int o = 0; o < 4; o++) {
        const int d = 2 * o + 1;
        float v[8];
        v[0] = accOs[o][0];
        UNPACK2(v[1], v[2], accO[o][0]);
        UNPACK2(v[3], v[4], accO[o][1]);
        UNPACK2(v[5], v[6], accO[o][2]);
        v[7] = accOs[o][1];
        float4 s0 = {v[0] * scale, v[1] * scale, v[2] * scale, v[3] * scale};
        float4 s1 = {v[4] * scale, v[5] * scale, v[6] * scale, v[7] * scale};
        *(float4*)(ob + (size_t)d * 4096)     = s0;
        *(float4*)(ob + (size_t)d * 4096 + 4) = s1;
    }
}

extern "C" void kernel_launch(void* const* d_in, const int* in_sizes, int n_in,
                              void* d_out, int out_size) {
    const float* x = (const float*)d_in[0];
    const float* y = (const float*)d_in[1];
    float* out = (float*)d_out;
    dim3 grid(32, 16);   // 32 i-tiles (TI=2) x 16 batches
    corr_kernel<<<grid, NTHREADS>>>(x, y, out);
}

// round 10
// speedup vs baseline: 1.0600x; 1.0600x over previous
#include <cuda_runtime.h>

// Spatial correlation: out[b, di*9+dj, i, j] = (1/256) * sum_c x[b,c,i,j] * y[b,c,i+di-4, j+dj-4]
// x,y: [16, 256, 64, 64] f32, zero padding.
//
// Round-9: 8-pixel FFMA2 threads, conflict-free sigma-padded smem, cp.async ring.
//   Thread: 8 j x 1 di x 9 dj = 72 acc floats as f32x2 pairs; parity-split so only
//   even-aligned y pairs are needed (= float4 halves, zero MOVs).
//   Block: 576 thr = 8jg x 9dg x 8ti, TI=8; grid 8x16=128 (single wave).
//   Smem layout: 16B chunk C placed at slot C+(C>>1) (16B pad per 32B) =>
//   lane jg chunk 2jg+K hits subbank 3jg+... : conflict-free LDS.128.
//   Ring: STAGES=3 x CPS=2 channels, 58368B dynamic smem, 128 barriers.

#define NTHREADS 576
#define YCH   6656      // y bytes per channel: 16 rows * 416
#define YROW  416       // 26 slots * 16
#define XCH   3072      // x bytes per channel: 8 rows * 384
#define XROW  384
#define XBASE 13312     // 2*YCH
#define STAGEB 19456    // 2*(YCH+XCH)
#define NSTAGES 128     // 256 channels / 2

#define FMA2(a, b, c) asm("fma.rn.f32x2 %0, %1, %2, %0;" : "+l"(a) : "l"(b), "l"(c))
#define PACK2(d, lo, hi) asm("mov.b64 %0, {%1, %2};" : "=l"(d) : "f"(lo), "f"(hi))

typedef unsigned long long ull;
union U4 { float4 v; ull u[2]; float f[4]; };
union U2 { ull u; float f[2]; };

__device__ __forceinline__ void cp16(unsigned saddr, const float* g, int nbytes) {
    asm volatile("cp.async.ca.shared.global [%0], [%1], 16, %2;\n"
                 :: "r"(saddr), "l"(g), "r"(nbytes));
}
#define COMMIT() asm volatile("cp.async.commit_group;\n" ::: "memory")
#define WAIT1()  asm volatile("cp.async.wait_group 1;\n" ::: "memory")

extern __shared__ char smdyn[];

__global__ __launch_bounds__(NTHREADS, 1)
void corr_kernel(const float* __restrict__ x,
                 const float* __restrict__ y,
                 float* __restrict__ out) {
    const int tid  = threadIdx.x;
    const int lane = tid & 31;
    const int warp = tid >> 5;
    const int jg = lane & 7;
    const int tl = lane >> 3;
    const int dg = warp % 9;
    const int w2 = warp / 9;
    const int ti = tl + 4 * w2;        // 0..7
    const int b   = blockIdx.y;
    const int gi0 = blockIdx.x * 8;
    const int j0  = jg * 8;
    const int ry  = ti + dg;           // y tile row 0..15

    const float* xb = x + (size_t)b * 1048576;
    const float* yb = y + (size_t)b * 1048576;
    const unsigned smb = (unsigned)__cvta_generic_to_shared(smdyn);

    // ---- cp.async chunk descriptors: 832 chunks/stage, <=2 per thread ----
    const float* gsrc0; const float* gsrc1 = xb;
    unsigned dst0, dst1 = 0; int nb0, nb1 = 0;
    {
        // chunk 0: q = tid (always < 832)
        int q = tid;
        if (q < 576) {
            int ch = q / 288, m = q % 288, r = m / 18, C = m % 18;
            int gr = gi0 - 4 + r;
            bool ok = (gr >= 0) && (gr < 64) && (C >= 1) && (C <= 16);
            nb0 = ok ? 16 : 0;
            gsrc0 = yb + ch * 4096 + (ok ? (gr * 64 + C * 4 - 4) : 0);
            dst0 = (unsigned)(ch * YCH + r * YROW + (C + (C >> 1)) * 16);
        } else {
            int q2 = q - 576, ch = q2 / 128, m = q2 % 128, r = m / 16, C = m % 16;
            nb0 = 16;
            gsrc0 = xb + ch * 4096 + (gi0 + r) * 64 + C * 4;
            dst0 = (unsigned)(XBASE + ch * XCH + r * XROW + (C + (C >> 1)) * 16);
        }
        // chunk 1: q = tid + 576, active iff tid < 256 (always y region? 576+255=831 -> could be x? 576..831: q>=576 -> x)
        if (tid < 256) {
            int q2 = tid;                 // q - 576
            if (tid + 576 < 576 + 384) {  // always true (q2 < 384): x region has 512 chunks? recompute generally:
            }
            // general: qq = tid + 576 in [576, 832): x chunk index q2 in [0,256)
            int ch = q2 / 128, m = q2 % 128, r = m / 16, C = m % 16;
            nb1 = 16;
            gsrc1 = xb + ch * 4096 + (gi0 + r) * 64 + C * 4;
            dst1 = (unsigned)(XBASE + ch * XCH + r * XROW + (C + (C >> 1)) * 16);
        }
    }

#define REFILL(S) do { \
    unsigned _bo = smb + (unsigned)(((S) % 3) * STAGEB); \
    cp16(_bo + dst0, gsrc0 + (size_t)(S) * 8192, nb0); \
    if (tid < 256) cp16(_bo + dst1, gsrc1 + (size_t)(S) * 8192, nb1); \
} while (0)

    // ---- accumulators ----
    ull accE[5][4];          // even dj=2e, pixel pairs (0,1)(2,3)(4,5)(6,7)
    ull accO[4][3];          // odd  dj=2o+1, pixel pairs (1,2)(3,4)(5,6)
    float accOs[4][2];       // odd dj edges: P0, P7
#pragma unroll
    for (int e = 0; e < 5; e++)
#pragma unroll
        for (int p = 0; p < 4; p++) accE[e][p] = 0ull;
#pragma unroll
    for (int o = 0; o < 4; o++) {
        accO[o][0] = accO[o][1] = accO[o][2] = 0ull;
        accOs[o][0] = accOs[o][1] = 0.0f;
    }

    // per-thread smem compute offsets
    const unsigned yoff = (unsigned)(ry * YROW + 48 * jg);
    const unsigned xoff = (unsigned)(XBASE + ti * XROW + 48 * jg);
    const char* smp = smdyn;

    REFILL(0); COMMIT();
    REFILL(1); COMMIT();

    for (int s = 0; s < NSTAGES; s++) {
        WAIT1();
        __syncthreads();
        if (s + 2 < NSTAGES) REFILL(s + 2);
        COMMIT();

        const char* st = smp + (s % 3) * STAGEB;
#pragma unroll
        for (int ch = 0; ch < 2; ch++) {
            const char* ys = st + ch * YCH + yoff;
            const char* xs = st + ch * XCH + xoff;

            U4 xa, xc;
            xa.v = *(const float4*)(xs);
            xc.v = *(const float4*)(xs + 16);
            ull xo0, xo1, xo2;
            PACK2(xo0, xa.f[1], xa.f[2]);
            PACK2(xo1, xa.f[3], xc.f[0]);
            PACK2(xo2, xc.f[1], xc.f[2]);
            const float x0 = xa.f[0], x7 = xc.f[3];

            U4 f;
            // K=0 : E0 = f.u[0] (w0,w1), E1 = f.u[1] (w2,w3)
            f.v = *(const float4*)(ys);
            FMA2(accE[0][0], xa.u[0], f.u[0]);
            accOs[0][0] = fmaf(x0, f.f[1], accOs[0][0]);
            FMA2(accE[0][1], xa.u[1], f.u[1]);
            FMA2(accE[1][0], xa.u[0], f.u[1]);
            FMA2(accO[0][0], xo0, f.u[1]);
            accOs[1][0] = fmaf(x0, f.f[3], accOs[1][0]);
            // K=1 : E2, E3
            f.v = *(const float4*)(ys + 16);
            FMA2(accE[0][2], xc.u[0], f.u[0]);
            FMA2(accE[1][1], xa.u[1], f.u[0]);
            FMA2(accE[2][0], xa.u[0], f.u[0]);
            FMA2(accO[0][1], xo1, f.u[0]);
            FMA2(accO[1][0], xo0, f.u[0]);
            accOs[2][0] = fmaf(x0, f.f[1], accOs[2][0]);
            FMA2(accE[0][3], xc.u[1], f.u[1]);
            FMA2(accE[1][2], xc.u[0], f.u[1]);
            FMA2(accE[2][1], xa.u[1], f.u[1]);
            FMA2(accE[3][0], xa.u[0], f.u[1]);
            FMA2(accO[0][2], xo2, f.u[1]);
            FMA2(accO[1][1], xo1, f.u[1]);
            FMA2(accO[2][0], xo0, f.u[1]);
            accOs[3][0] = fmaf(x0, f.f[3], accOs[3][0]);
            // K=2 : E4, E5
            f.v = *(const float4*)(ys + 48);
            FMA2(accE[1][3], xc.u[1], f.u[0]);
            FMA2(accE[2][2], xc.u[0], f.u[0]);
            FMA2(accE[3][1], xa.u[1], f.u[0]);
            FMA2(accE[4][0], xa.u[0], f.u[0]);
            FMA2(accO[1][2], xo2, f.u[0]);
            FMA2(accO[2][1], xo1, f.u[0]);
            FMA2(accO[3][0], xo0, f.u[0]);
            accOs[0][1] = fmaf(x7, f.f[0], accOs[0][1]);
            FMA2(accE[2][3], xc.u[1], f.u[1]);
            FMA2(accE[3][2], xc.u[0], f.u[1]);
            FMA2(accE[4][1], xa.u[1], f.u[1]);
            FMA2(accO[2][2], xo2, f.u[1]);
            FMA2(accO[3][1], xo1, f.u[1]);
            accOs[1][1] = fmaf(x7, f.f[2], accOs[1][1]);
            // K=3 : E6, E7
            f.v = *(const float4*)(ys + 64);
            FMA2(accE[3][3], xc.u[1], f.u[0]);
            FMA2(accE[4][2], xc.u[0], f.u[0]);
            FMA2(accO[3][2], xo2, f.u[0]);
            accOs[2][1] = fmaf(x7, f.f[0], accOs[2][1]);
            FMA2(accE[4][3], xc.u[1], f.u[1]);
            accOs[3][1] = fmaf(x7, f.f[2], accOs[3][1]);
        }
    }

    // ---- epilogue: scale 1/256, coalesced float4 stores ----
    const float sc = 1.0f / 256.0f;
    const int i = gi0 + ti;
    float* ob = out + ((size_t)b * 81 + dg * 9) * 4096 + i * 64 + j0;
#pragma unroll
    for (int e = 0; e < 5; e++) {
        const int d = 2 * e;
        U4 t0, t1;
        t0.u[0] = accE[e][0]; t0.u[1] = accE[e][1];
        t1.u[0] = accE[e][2]; t1.u[1] = accE[e][3];
        float4 s0 = {t0.f[0] * sc, t0.f[1] * sc, t0.f[2] * sc, t0.f[3] * sc};
        float4 s1 = {t1.f[0] * sc, t1.f[1] * sc, t1.f[2] * sc, t1.f[3] * sc};
        *(float4*)(ob + (size_t)d * 4096)     = s0;
        *(float4*)(ob + (size_t)d * 4096 + 4) = s1;
    }
#pragma unroll
    for (int o = 0; o < 4; o++) {
        const int d = 2 * o + 1;
        U2 a0, a1, a2;
        a0.u = accO[o][0]; a1.u = accO[o][1]; a2.u = accO[o][2];
        float4 s0 = {accOs[o][0] * sc, a0.f[0] * sc, a0.f[1] * sc, a1.f[0] * sc};
        float4 s1 = {a1.f[1] * sc, a2.f[0] * sc, a2.f[1] * sc, accOs[o][1] * sc};
        *(float4*)(ob + (size_t)d * 4096)     = s0;
        *(float4*)(ob + (size_t)d * 4096 + 4) = s1;
    }
}

extern "C" void kernel_launch(void* const* d_in, const int* in_sizes, int n_in,
                              void* d_out, int out_size) {
    const float* x = (const float*)d_in[0];
    const float* y = (const float*)d_in[1];
    float* out = (float*)d_out;
    cudaFuncSetAttribute(corr_kernel, cudaFuncAttributeMaxDynamicSharedMemorySize,
                         3 * STAGEB);
    dim3 grid(8, 16);   // 8 i-tiles (TI=8) x 16 batches
    corr_kernel<<<grid, NTHREADS, 3 * STAGEB>>>(x, y, out);
}

// round 11
// speedup vs baseline: 1.6641x; 1.5699x over previous
#include <cuda_runtime.h>

// Spatial correlation: out[b, di*9+dj, i, j] = (1/256) * sum_c x[b,c,i,j] * y[b,c,i+di-4, j+dj-4]
// x,y: [16, 256, 64, 64] f32, zero padding.
//
// Round-11: R5 inner loop (proven), rebalanced for occupancy + deeper prefetch.
//   Thread: 4 j-pixels x 1 di x 9 dj = 36 fp32 accumulators (~83 regs).
//   Block: 288 threads = 16 jg x 9 dg x 2 ti, tile = 2 rows x 64 cols.
//   Grid: 32 i-tiles x 16 batches = 512 blocks, 2 resident blocks/SM.
//   Smem ring: 4 stages x 2 channels x (y 10x72 + x 2x64), prefetch distance 3 stages.

#define TI       2
#define SROWS    10            // TI + 8 halo rows
#define SCOLS    72            // 64 + 8 halo cols
#define YF       (SROWS * SCOLS)   // 720 floats per channel (y tile)
#define XF       (TI * 64)         // 128 floats per channel (x tile)
#define CPS      2                 // channels per stage
#define STAGE_F  (CPS * (YF + XF)) // 1696 floats per stage
#define STAGES   4
#define NTHREADS 288
#define NCHUNK   (CPS * (YF / 4 + XF / 4))  // 424 16B chunks per stage
#define NSTAGE_TOT 128             // 256 channels / CPS

__device__ __forceinline__ void cp16(unsigned saddr, const float* g, int nbytes) {
    asm volatile("cp.async.ca.shared.global [%0], [%1], 16, %2;\n"
                 :: "r"(saddr), "l"(g), "r"(nbytes));
}
#define COMMIT() asm volatile("cp.async.commit_group;\n" ::: "memory")
#define WAIT2()  asm volatile("cp.async.wait_group 2;\n" ::: "memory")

__global__ __launch_bounds__(NTHREADS, 2)
void corr_kernel(const float* __restrict__ x,
                 const float* __restrict__ y,
                 float* __restrict__ out) {
    __shared__ __align__(16) float sm[STAGES * STAGE_F];   // 27136 B

    const int tid = threadIdx.x;
    const int jg  = tid & 15;          // 0..15 : j-group (4 pixels)
    const int dg  = (tid >> 4) % 9;    // 0..8  : di
    const int ti  = tid / 144;         // 0..1  : row within tile
    const int b   = blockIdx.y;
    const int gi0 = blockIdx.x * TI;
    const int j0  = jg * 4;

    const float* xb = x + (size_t)b * 1048576;
    const float* yb = y + (size_t)b * 1048576;
    const unsigned smbase = (unsigned)__cvta_generic_to_shared(sm);

    // ---- per-thread chunk assignment: 424 chunks/stage, <=2 per thread ----
    // stage float layout: [y ch0 : 720][y ch1 : 720][x ch0 : 128][x ch1 : 128]
    const float* gsrc0; unsigned dst0; int nb0;
    const float* gsrc1 = xb; unsigned dst1 = 0; int nb1 = 0;
    {
        // chunk 0: q = tid in [0,288) -> always a y chunk (y has 360 chunks)
        int q = tid;
        int ch = q / 180, m = q % 180;
        int r  = m / 18,  c4 = m % 18;    // smem col = c4*4, global col = c4*4-4
        int gr = gi0 - 4 + r;
        bool ok = (gr >= 0) && (gr < 64) && (c4 >= 1) && (c4 <= 16);
        nb0   = ok ? 16 : 0;
        gsrc0 = yb + ch * 4096 + (ok ? (gr * 64 + c4 * 4 - 4) : 0);
        dst0  = (unsigned)((ch * YF + r * SCOLS + c4 * 4) * 4);
    }
    if (tid < NCHUNK - NTHREADS) {       // tid < 136 : second chunk q = tid + 288
        int q = tid + NTHREADS;
        if (q < 2 * (YF / 4)) {          // y chunk (q in [288,360))
            int ch = q / 180, m = q % 180;
            int r  = m / 18,  c4 = m % 18;
            int gr = gi0 - 4 + r;
            bool ok = (gr >= 0) && (gr < 64) && (c4 >= 1) && (c4 <= 16);
            nb1   = ok ? 16 : 0;
            gsrc1 = yb + ch * 4096 + (ok ? (gr * 64 + c4 * 4 - 4) : 0);
            dst1  = (unsigned)((ch * YF + r * SCOLS + c4 * 4) * 4);
        } else {                         // x chunk (q in [360,424))
            int q2 = q - 2 * (YF / 4);   // 0..63
            int ch = q2 / 32, m = q2 % 32;
            int r  = m / 16,  cc = m % 16;
            nb1   = 16;
            gsrc1 = xb + ch * 4096 + (gi0 + r) * 64 + cc * 4;
            dst1  = (unsigned)((2 * YF + ch * XF + r * 64 + cc * 4) * 4);
        }
    }

#define REFILL(S) do { \
    unsigned _bo = smbase + (unsigned)(((S) % STAGES) * (STAGE_F * 4)); \
    cp16(_bo + dst0, gsrc0 + (size_t)(S) * (CPS * 4096), nb0); \
    if (tid < NCHUNK - NTHREADS) \
        cp16(_bo + dst1, gsrc1 + (size_t)(S) * (CPS * 4096), nb1); \
} while (0)

    float acc[9][4];
#pragma unroll
    for (int d = 0; d < 9; d++)
#pragma unroll
        for (int q = 0; q < 4; q++) acc[d][q] = 0.0f;

    // ---- prologue: 3 stages in flight ----
    REFILL(0); COMMIT();
    REFILL(1); COMMIT();
    REFILL(2); COMMIT();

    // ---- main loop over 128 stages (256 channels) ----
    for (int s = 0; s < NSTAGE_TOT; s++) {
        WAIT2();                 // stage s landed (all but last 2 groups)
        __syncthreads();
        if (s + STAGES - 1 < NSTAGE_TOT) REFILL(s + STAGES - 1);
        COMMIT();

        const float* st = sm + (s % STAGES) * STAGE_F;
#pragma unroll
        for (int ch = 0; ch < CPS; ch++) {
            const float* ybuf = st + ch * YF;
            const float* xbuf = st + 2 * YF + ch * XF;
            float4 xv = *(const float4*)(xbuf + ti * 64 + j0);
            const float* yr = ybuf + (ti + dg) * SCOLS + j0;
            float4 w0 = *(const float4*)(yr + 0);
            float4 w1 = *(const float4*)(yr + 4);
            float4 w2 = *(const float4*)(yr + 8);
            float wv[12] = {w0.x, w0.y, w0.z, w0.w,
                            w1.x, w1.y, w1.z, w1.w,
                            w2.x, w2.y, w2.z, w2.w};
#pragma unroll
            for (int d = 0; d < 9; d++) {
                acc[d][0] += xv.x * wv[d + 0];
                acc[d][1] += xv.y * wv[d + 1];
                acc[d][2] += xv.z * wv[d + 2];
                acc[d][3] += xv.w * wv[d + 3];
            }
        }
    }

    // ---- epilogue: scale by 1/256, coalesced float4 stores ----
    const float scale = 1.0f / 256.0f;
    float* ob = out + (size_t)b * 81 * 4096;
    const int i = gi0 + ti;
#pragma unroll
    for (int d = 0; d < 9; d++) {
        const int p = dg * 9 + d;
        float4 v;
        v.x = acc[d][0] * scale;
        v.y = acc[d][1] * scale;
        v.z = acc[d][2] * scale;
        v.w = acc[d][3] * scale;
        *(float4*)(ob + (size_t)p * 4096 + i * 64 + j0) = v;
    }
}

extern "C" void kernel_launch(void* const* d_in, const int* in_sizes, int n_in,
                              void* d_out, int out_size) {
    const float* x = (const float*)d_in[0];
    const float* y = (const float*)d_in[1];
    float* out = (float*)d_out;
    dim3 grid(32, 16);   // 32 i-tiles (TI=2) x 16 batches
    corr_kernel<<<grid, NTHREADS>>>(x, y, out);
}